// round 2
// baseline (speedup 1.0000x reference)
#include <cuda_runtime.h>
#include <math.h>

#define BB 8
#define SS 4096
#define DD 1024
#define NN 64
#define SHIFT 2048
#define NCH 128
#define CHL 32
#define TILE_T 32

// ---------------- scratch (device globals) ----------------
__device__ float g_wT[DD * 128];            // [d][o]: o=2n -> lnw*kw, o=2n+1 -> lnw*vw
__device__ float g_wsum[128];
__device__ float g_lbsum[128];
__device__ float g_gate[DD];
__device__ float g_w[NN];                   // exp(time_decay)
__device__ float g_exptf[NN];               // exp(time_first)
__device__ float4 g_owQ[16 * DD];           // [n4][d] = ow[d][4n4..4n4+3]
__device__ float g_wkv[BB * SS * NN];
__device__ float g_chunk[BB * NCH * NN];
__device__ float g_carry[BB * NCH * NN];

// ---------------- packed fp32x2 FMA (sm_103a FFMA2) ----------------
__device__ __forceinline__ float2 ffma2(float2 a, float2 b, float2 c) {
    float2 d;
    asm("fma.rn.f32x2 %0, %1, %2, %3;"
        : "=l"(*reinterpret_cast<unsigned long long*>(&d))
        : "l"(*reinterpret_cast<unsigned long long*>(&a)),
          "l"(*reinterpret_cast<unsigned long long*>(&b)),
          "l"(*reinterpret_cast<unsigned long long*>(&c)));
    return d;
}

// ---------------- prep kernels ----------------
__global__ void prep_a(const float* __restrict__ kw, const float* __restrict__ vw,
                       const float* __restrict__ lnw, const float* __restrict__ tsg,
                       const float* __restrict__ td, const float* __restrict__ tf) {
    int idx = blockIdx.x * 256 + threadIdx.x;   // 0..131071
    int d = idx >> 7;
    int o = idx & 127;
    int n = o >> 1;
    const float* src = (o & 1) ? vw : kw;
    g_wT[idx] = lnw[d] * src[n * DD + d];
    if (o == 0) g_gate[d] = 1.f / (1.f + expf(-tsg[d]));
    if (idx < NN) g_w[idx] = expf(td[idx]);
    else if (idx < 2 * NN) g_exptf[idx - NN] = expf(tf[idx - NN]);
}

__global__ void prep_ow(const float* __restrict__ ow) {
    int idx = blockIdx.x * 256 + threadIdx.x;   // 0..16383
    int d = idx & (DD - 1);
    int n4 = idx >> 10;
    g_owQ[idx] = *reinterpret_cast<const float4*>(&ow[d * NN + 4 * n4]);
}

// one block per output column o; 256 threads reduce over d
__global__ void prep_b(const float* __restrict__ kw, const float* __restrict__ vw,
                       const float* __restrict__ lnb) {
    __shared__ float red[2][8];
    int o = blockIdx.x;
    int n = o >> 1;
    const float* src = (o & 1) ? vw : kw;
    int tid = threadIdx.x;
    float ws = 0.f, lb = 0.f;
    for (int d = tid; d < DD; d += 256) {
        ws += g_wT[d * 128 + o];
        lb += lnb[d] * src[n * DD + d];
    }
#pragma unroll
    for (int off = 16; off; off >>= 1) {
        ws += __shfl_xor_sync(0xffffffffu, ws, off);
        lb += __shfl_xor_sync(0xffffffffu, lb, off);
    }
    if ((tid & 31) == 0) { red[0][tid >> 5] = ws; red[1][tid >> 5] = lb; }
    __syncthreads();
    if (tid == 0) {
        float a = 0.f, c = 0.f;
#pragma unroll
        for (int i = 0; i < 8; i++) { a += red[0][i]; c += red[1][i]; }
        g_wsum[o] = a;
        g_lbsum[o] = c;
    }
}

// ---------------- kernel A: shift + LN(folded) + KV proj + wkv + chunk sums ----------------
// grid: BB * (SS/32) = 1024 blocks, 512 threads
// smem: xs[32*1024] (128KB) | wsm[128*128] (64KB, overlaid by wkv_s[32*64] in epilogue)
__global__ void __launch_bounds__(512, 1)
kernelA(const float* __restrict__ x) {
    extern __shared__ float sm[];
    float* xs_s = sm;                       // 32768 floats
    float* wsm = sm + TILE_T * DD;          // 16384 floats

    int b = blockIdx.x >> 7;
    int cb = blockIdx.x & 127;
    int t0 = cb * TILE_T;
    int tid = threadIdx.x;
    int lane = tid & 31;
    int warp = tid >> 5;
    int r0 = warp * 2;

    // ---- token shift + LN stats (kept in registers per warp) ----
    float mu_r[2], inv_r[2];
#pragma unroll
    for (int i = 0; i < 2; i++) {
        int r = r0 + i;
        int t = t0 + r;
        int tc = t ^ SHIFT;
        const float4* xt = reinterpret_cast<const float4*>(x + ((size_t)(b * SS + t)) * DD);
        const float4* xc = reinterpret_cast<const float4*>(x + ((size_t)(b * SS + tc)) * DD);
        const float4* gp = reinterpret_cast<const float4*>(g_gate);
        float4 vals[8];
        float sum = 0.f, sq = 0.f;
#pragma unroll
        for (int j = 0; j < 8; j++) {
            int e = j * 32 + lane;
            float4 xv = xt[e], xcv = xc[e], g = gp[e];
            float4 s;
            s.x = xv.x + g.x * (xcv.x - xv.x);
            s.y = xv.y + g.y * (xcv.y - xv.y);
            s.z = xv.z + g.z * (xcv.z - xv.z);
            s.w = xv.w + g.w * (xcv.w - xv.w);
            vals[j] = s;
            sum += s.x + s.y + s.z + s.w;
            sq += s.x * s.x + s.y * s.y + s.z * s.z + s.w * s.w;
        }
#pragma unroll
        for (int off = 16; off; off >>= 1) {
            sum += __shfl_xor_sync(0xffffffffu, sum, off);
            sq  += __shfl_xor_sync(0xffffffffu, sq, off);
        }
        float mu = sum * (1.f / DD);
        float var = sq * (1.f / DD) - mu * mu;
        mu_r[i] = mu;
        inv_r[i] = rsqrtf(var + 1e-5f);
        float4* dst = reinterpret_cast<float4*>(&xs_s[r * DD]);
#pragma unroll
        for (int j = 0; j < 8; j++) dst[j * 32 + lane] = vals[j];
    }

    // ---- GEMM: 32x1024 @ 1024x128 (interleaved k,v columns) ----
    float2 acc[2][2];
    acc[0][0] = make_float2(0.f, 0.f); acc[0][1] = make_float2(0.f, 0.f);
    acc[1][0] = make_float2(0.f, 0.f); acc[1][1] = make_float2(0.f, 0.f);

    for (int ch = 0; ch < 8; ch++) {
        __syncthreads();
        {   // stage 128x128 weight chunk (contiguous copy)
            const float4* src = reinterpret_cast<const float4*>(&g_wT[ch * 128 * 128]);
            float4* dst = reinterpret_cast<float4*>(wsm);
#pragma unroll
            for (int q = 0; q < 8; q++) dst[q * 512 + tid] = src[q * 512 + tid];
        }
        __syncthreads();

        const float* aP0 = &xs_s[r0 * DD + ch * 128];
        const float* aP1 = aP0 + DD;
#pragma unroll 8
        for (int dl = 0; dl < 128; dl += 4) {
            float4 a0 = *reinterpret_cast<const float4*>(aP0 + dl);
            float4 a1 = *reinterpret_cast<const float4*>(aP1 + dl);
            const float2* w0 = reinterpret_cast<const float2*>(&wsm[(dl + 0) * 128 + lane * 4]);
            const float2* w1 = reinterpret_cast<const float2*>(&wsm[(dl + 1) * 128 + lane * 4]);
            const float2* w2 = reinterpret_cast<const float2*>(&wsm[(dl + 2) * 128 + lane * 4]);
            const float2* w3 = reinterpret_cast<const float2*>(&wsm[(dl + 3) * 128 + lane * 4]);
            float4 wa = *reinterpret_cast<const float4*>(w0);
            float4 wb = *reinterpret_cast<const float4*>(w1);
            float4 wc = *reinterpret_cast<const float4*>(w2);
            float4 wd = *reinterpret_cast<const float4*>(w3);
            float2 av;
            av = make_float2(a0.x, a0.x);
            acc[0][0] = ffma2(av, make_float2(wa.x, wa.y), acc[0][0]);
            acc[0][1] = ffma2(av, make_float2(wa.z, wa.w), acc[0][1]);
            av = make_float2(a1.x, a1.x);
            acc[1][0] = ffma2(av, make_float2(wa.x, wa.y), acc[1][0]);
            acc[1][1] = ffma2(av, make_float2(wa.z, wa.w), acc[1][1]);
            av = make_float2(a0.y, a0.y);
            acc[0][0] = ffma2(av, make_float2(wb.x, wb.y), acc[0][0]);
            acc[0][1] = ffma2(av, make_float2(wb.z, wb.w), acc[0][1]);
            av = make_float2(a1.y, a1.y);
            acc[1][0] = ffma2(av, make_float2(wb.x, wb.y), acc[1][0]);
            acc[1][1] = ffma2(av, make_float2(wb.z, wb.w), acc[1][1]);
            av = make_float2(a0.z, a0.z);
            acc[0][0] = ffma2(av, make_float2(wc.x, wc.y), acc[0][0]);
            acc[0][1] = ffma2(av, make_float2(wc.z, wc.w), acc[0][1]);
            av = make_float2(a1.z, a1.z);
            acc[1][0] = ffma2(av, make_float2(wc.x, wc.y), acc[1][0]);
            acc[1][1] = ffma2(av, make_float2(wc.z, wc.w), acc[1][1]);
            av = make_float2(a0.w, a0.w);
            acc[0][0] = ffma2(av, make_float2(wd.x, wd.y), acc[0][0]);
            acc[0][1] = ffma2(av, make_float2(wd.z, wd.w), acc[0][1]);
            av = make_float2(a1.w, a1.w);
            acc[1][0] = ffma2(av, make_float2(wd.x, wd.y), acc[1][0]);
            acc[1][1] = ffma2(av, make_float2(wd.z, wd.w), acc[1][1]);
        }
    }

    // ---- epilogue: LN fold finish + wkv; store to gmem + smem for chunk sums ----
    __syncthreads();                        // all wsm reads done; overlay
    float* wkv_s = wsm;                     // 32*64
#pragma unroll
    for (int i = 0; i < 2; i++) {
        int r = r0 + i;
        int t = t0 + r;
        float mu = mu_r[i], inv = inv_r[i];
        int n0 = 2 * lane;
        float k0 = inv * (acc[i][0].x - mu * g_wsum[2 * n0])     + g_lbsum[2 * n0];
        float v0 = inv * (acc[i][0].y - mu * g_wsum[2 * n0 + 1]) + g_lbsum[2 * n0 + 1];
        float wk0 = expf(-g_exptf[n0] * k0) * v0;
        int n1 = n0 + 1;
        float k1 = inv * (acc[i][1].x - mu * g_wsum[2 * n1])     + g_lbsum[2 * n1];
        float v1 = inv * (acc[i][1].y - mu * g_wsum[2 * n1 + 1]) + g_lbsum[2 * n1 + 1];
        float wk1 = expf(-g_exptf[n1] * k1) * v1;
        float2 wv = make_float2(wk0, wk1);
        *reinterpret_cast<float2*>(&g_wkv[((size_t)(b * SS + t)) * NN + n0]) = wv;
        *reinterpret_cast<float2*>(&wkv_s[r * NN + n0]) = wv;
    }
    __syncthreads();
    if (tid < NN) {
        int n = tid;
        float w = g_w[n];
        float a = 0.f;
#pragma unroll
        for (int r = 0; r < TILE_T; r++) a = a * w + wkv_s[r * NN + n];
        g_chunk[(b * NCH + cb) * NN + n] = a;
    }
}

// ---------------- carry prefix over chunks ----------------
__global__ void scan_carry(const float* __restrict__ td, float* __restrict__ lastout,
                           int write_last) {
    int tid = threadIdx.x;                  // 512 threads
    int n = tid & (NN - 1);
    int b = tid >> 6;
    float wL = expf((float)CHL * td[n]);
    float carry = 0.f;
    for (int c = 0; c < NCH; c++) {
        g_carry[(b * NCH + c) * NN + n] = carry;
        carry = carry * wL + g_chunk[(b * NCH + c) * NN + n];
    }
    if (write_last) lastout[b * NN + n] = carry;
}

// ---------------- kernel C: fused scan + output projection ----------------
// grid: BB*128*2 = 2048 blocks, 512 threads; thread owns one d (half split)
__global__ void __launch_bounds__(512, 1)
kernelC(float* __restrict__ out) {
    extern __shared__ float s_sm[];         // 32*64 floats
    int half = blockIdx.x & 1;
    int rb = blockIdx.x >> 1;
    int b = rb >> 7;
    int c = rb & 127;
    int t0 = c * TILE_T;
    int tid = threadIdx.x;

    // load wkv tile (2048 floats)
    reinterpret_cast<float4*>(s_sm)[tid] =
        reinterpret_cast<const float4*>(&g_wkv[((size_t)(b * SS + t0)) * NN])[tid];
    __syncthreads();

    // in-place scan: wkv -> states (threads 0..63, one per n)
    if (tid < NN) {
        int n = tid;
        float w = g_w[n];
        float st = g_carry[(b * NCH + c) * NN + n];
#pragma unroll
        for (int r = 0; r < TILE_T; r++) {
            st = st * w + s_sm[r * NN + n];
            s_sm[r * NN + n] = st;
        }
    }
    __syncthreads();

    // GEMM: out[r][d] = sum_n states[r][n] * ow[d][n]
    int d = half * 512 + tid;
    float2 acc[TILE_T];
#pragma unroll
    for (int r = 0; r < TILE_T; r++) acc[r] = make_float2(0.f, 0.f);

#pragma unroll 2
    for (int n4 = 0; n4 < 16; n4++) {
        float4 w4 = __ldg(&g_owQ[n4 * DD + d]);
        float2 wlo = make_float2(w4.x, w4.y);
        float2 whi = make_float2(w4.z, w4.w);
#pragma unroll
        for (int r = 0; r < TILE_T; r++) {
            float4 s4 = *reinterpret_cast<const float4*>(&s_sm[r * NN + 4 * n4]);
            acc[r] = ffma2(make_float2(s4.x, s4.y), wlo, acc[r]);
            acc[r] = ffma2(make_float2(s4.z, s4.w), whi, acc[r]);
        }
    }

    float* ob = out + ((size_t)(b * SS + t0)) * DD + d;
#pragma unroll
    for (int r = 0; r < TILE_T; r++)
        ob[(size_t)r * DD] = acc[r].x + acc[r].y;
}

// ---------------- launch ----------------
extern "C" void kernel_launch(void* const* d_in, const int* in_sizes, int n_in,
                              void* d_out, int out_size) {
    const float* x   = (const float*)d_in[0];
    const float* td  = (const float*)d_in[1];
    const float* tf  = (const float*)d_in[2];
    const float* kw  = (const float*)d_in[3];
    const float* vw  = (const float*)d_in[4];
    const float* ow  = (const float*)d_in[5];
    const float* tsg = (const float*)d_in[6];
    const float* lnw = (const float*)d_in[7];
    const float* lnb = (const float*)d_in[8];
    float* out = (float*)d_out;

    const int SMEM_A = (TILE_T * DD + 128 * 128) * (int)sizeof(float);   // 196608
    const int SMEM_C = (TILE_T * NN) * (int)sizeof(float);               // 8192
    cudaFuncSetAttribute(kernelA, cudaFuncAttributeMaxDynamicSharedMemorySize, SMEM_A);
    cudaFuncSetAttribute(kernelC, cudaFuncAttributeMaxDynamicSharedMemorySize, SMEM_C);

    prep_a<<<(DD * 128) / 256, 256>>>(kw, vw, lnw, tsg, td, tf);
    prep_ow<<<64, 256>>>(ow);
    prep_b<<<128, 256>>>(kw, vw, lnb);
    kernelA<<<BB * (SS / TILE_T), 512, SMEM_A>>>(x);
    int write_last = (out_size >= BB * SS * DD + BB * NN) ? 1 : 0;
    scan_carry<<<1, 512>>>(td, out + (size_t)BB * SS * DD, write_last);
    kernelC<<<BB * (SS / TILE_T) * 2, 512, SMEM_C>>>(out);
}

// round 5
// speedup vs baseline: 1.7717x; 1.7717x over previous
#include <cuda_runtime.h>
#include <math.h>

#define BB 8
#define SS 4096
#define DD 1024
#define NN 64
#define SHIFT 2048
#define NCH 128
#define CHL 32
#define TILE_A 128
#define TILE_C 32

// ---------------- scratch (device globals) ----------------
__device__ float g_wT[DD * 128];            // [d][o]: o=2n -> lnw*kw, o=2n+1 -> lnw*vw
__device__ float g_wsum[128];
__device__ float g_lbsum[128];
__device__ float g_gate[DD];
__device__ float g_w[NN];                   // exp(time_decay)
__device__ float g_exptf[NN];               // exp(time_first)
__device__ float4 g_owQ[16 * DD];           // [n4][d] = ow[d][4n4..4n4+3]
__device__ float g_wkv[BB * SS * NN];
__device__ float g_chunk[BB * NCH * NN];
__device__ float g_carry[BB * NCH * NN];

// ---------------- packed fp32x2 FMA (sm_103a FFMA2) ----------------
__device__ __forceinline__ float2 ffma2(float2 a, float2 b, float2 c) {
    float2 d;
    asm("fma.rn.f32x2 %0, %1, %2, %3;"
        : "=l"(*reinterpret_cast<unsigned long long*>(&d))
        : "l"(*reinterpret_cast<unsigned long long*>(&a)),
          "l"(*reinterpret_cast<unsigned long long*>(&b)),
          "l"(*reinterpret_cast<unsigned long long*>(&c)));
    return d;
}

// ---------------- prep kernels ----------------
__global__ void prep_a(const float* __restrict__ kw, const float* __restrict__ vw,
                       const float* __restrict__ lnw, const float* __restrict__ tsg,
                       const float* __restrict__ td, const float* __restrict__ tf) {
    int idx = blockIdx.x * 256 + threadIdx.x;   // 0..131071
    int d = idx >> 7;
    int o = idx & 127;
    int n = o >> 1;
    const float* src = (o & 1) ? vw : kw;
    g_wT[idx] = lnw[d] * src[n * DD + d];
    if (o == 0) g_gate[d] = 1.f / (1.f + expf(-tsg[d]));
    if (idx < NN) g_w[idx] = expf(td[idx]);
    else if (idx < 2 * NN) g_exptf[idx - NN] = expf(tf[idx - NN]);
}

__global__ void prep_ow(const float* __restrict__ ow) {
    int idx = blockIdx.x * 256 + threadIdx.x;   // 0..16383
    int d = idx & (DD - 1);
    int n4 = idx >> 10;
    g_owQ[idx] = *reinterpret_cast<const float4*>(&ow[d * NN + 4 * n4]);
}

__global__ void prep_b(const float* __restrict__ kw, const float* __restrict__ vw,
                       const float* __restrict__ lnb) {
    __shared__ float red[2][8];
    int o = blockIdx.x;
    int n = o >> 1;
    const float* src = (o & 1) ? vw : kw;
    int tid = threadIdx.x;
    float ws = 0.f, lb = 0.f;
    for (int d = tid; d < DD; d += 256) {
        ws += g_wT[d * 128 + o];
        lb += lnb[d] * src[n * DD + d];
    }
#pragma unroll
    for (int off = 16; off; off >>= 1) {
        ws += __shfl_xor_sync(0xffffffffu, ws, off);
        lb += __shfl_xor_sync(0xffffffffu, lb, off);
    }
    if ((tid & 31) == 0) { red[0][tid >> 5] = ws; red[1][tid >> 5] = lb; }
    __syncthreads();
    if (tid == 0) {
        float a = 0.f, c = 0.f;
#pragma unroll
        for (int i = 0; i < 8; i++) { a += red[0][i]; c += red[1][i]; }
        g_wsum[o] = a;
        g_lbsum[o] = c;
    }
}

// ---------------- kernel A: blend + LN(folded) + KV proj + wkv + chunk sums ----------------
// grid: BB*(SS/128) = 256 blocks, 512 threads
// smem: wsm[128*128] (64KB) | xs[128*128] (64KB) | mu[128] | inv[128]
__global__ void __launch_bounds__(512, 1)
kernelA(const float* __restrict__ x) {
    extern __shared__ float sm[];
    float* wsm = sm;                 // 16384 floats
    float* xs  = sm + 16384;         // 16384 floats
    float* mu_s = sm + 32768;        // 128
    float* inv_s = mu_s + 128;       // 128

    int b = blockIdx.x >> 5;
    int cb = blockIdx.x & 31;
    int t0 = cb * TILE_A;
    int tid = threadIdx.x;
    int lane = tid & 31;
    int warp = tid >> 5;

    float st_sum[8], st_sq[8];
#pragma unroll
    for (int e = 0; e < 8; e++) { st_sum[e] = 0.f; st_sq[e] = 0.f; }

    float2 acc[8][2];
#pragma unroll
    for (int i = 0; i < 8; i++) { acc[i][0] = make_float2(0.f, 0.f); acc[i][1] = make_float2(0.f, 0.f); }

    for (int ch = 0; ch < 8; ch++) {
        __syncthreads();
        // stage weight chunk (128 d x 128 cols = 4096 float4)
        {
            const float4* src = reinterpret_cast<const float4*>(&g_wT[ch * 16384]);
            float4* dst = reinterpret_cast<float4*>(wsm);
#pragma unroll
            for (int q = 0; q < 8; q++) dst[q * 512 + tid] = src[q * 512 + tid];
        }
        // stage xs chunk with blend + stats
#pragma unroll
        for (int e = 0; e < 8; e++) {
            int idx = e * 512 + tid;          // 0..4095
            int row = idx >> 5;               // = e*16 + warp
            int c4 = idx & 31;
            int t = t0 + row;
            size_t base  = ((size_t)(b * SS) + t) * DD + ch * 128 + c4 * 4;
            size_t basec = ((size_t)(b * SS) + (t ^ SHIFT)) * DD + ch * 128 + c4 * 4;
            float4 xv = *reinterpret_cast<const float4*>(x + base);
            float4 xc = *reinterpret_cast<const float4*>(x + basec);
            float4 g  = *reinterpret_cast<const float4*>(&g_gate[ch * 128 + c4 * 4]);
            float4 s;
            s.x = xv.x + g.x * (xc.x - xv.x);
            s.y = xv.y + g.y * (xc.y - xv.y);
            s.z = xv.z + g.z * (xc.z - xv.z);
            s.w = xv.w + g.w * (xc.w - xv.w);
            st_sum[e] += s.x + s.y + s.z + s.w;
            st_sq[e]  += s.x * s.x + s.y * s.y + s.z * s.z + s.w * s.w;
            *reinterpret_cast<float4*>(&xs[row * 128 + c4 * 4]) = s;
        }
        __syncthreads();

        if (ch == 7) {
            // finalize LN stats: lanes of warp w hold rows {e*16+warp}
#pragma unroll
            for (int e = 0; e < 8; e++) {
                float s = st_sum[e], q = st_sq[e];
#pragma unroll
                for (int off = 16; off; off >>= 1) {
                    s += __shfl_xor_sync(0xffffffffu, s, off);
                    q += __shfl_xor_sync(0xffffffffu, q, off);
                }
                if (lane == 0) {
                    int row = e * 16 + warp;
                    float mu = s * (1.f / DD);
                    float var = q * (1.f / DD) - mu * mu;
                    mu_s[row] = mu;
                    inv_s[row] = rsqrtf(var + 1e-5f);
                }
            }
        }

        // GEMM over this chunk: warp owns rows warp*8..+7, lane owns cols lane*4..+3
        const float* aB = &xs[(warp * 8) * 128];
#pragma unroll 8
        for (int dl4 = 0; dl4 < 32; dl4++) {
            float4 wv[4];
#pragma unroll
            for (int k = 0; k < 4; k++)
                wv[k] = *reinterpret_cast<const float4*>(&wsm[(dl4 * 4 + k) * 128 + lane * 4]);
            float4 av[8];
#pragma unroll
            for (int i = 0; i < 8; i++)
                av[i] = *reinterpret_cast<const float4*>(&aB[i * 128 + dl4 * 4]);
#pragma unroll
            for (int i = 0; i < 8; i++) {
                float2 p;
                p = make_float2(av[i].x, av[i].x);
                acc[i][0] = ffma2(p, make_float2(wv[0].x, wv[0].y), acc[i][0]);
                acc[i][1] = ffma2(p, make_float2(wv[0].z, wv[0].w), acc[i][1]);
                p = make_float2(av[i].y, av[i].y);
                acc[i][0] = ffma2(p, make_float2(wv[1].x, wv[1].y), acc[i][0]);
                acc[i][1] = ffma2(p, make_float2(wv[1].z, wv[1].w), acc[i][1]);
                p = make_float2(av[i].z, av[i].z);
                acc[i][0] = ffma2(p, make_float2(wv[2].x, wv[2].y), acc[i][0]);
                acc[i][1] = ffma2(p, make_float2(wv[2].z, wv[2].w), acc[i][1]);
                p = make_float2(av[i].w, av[i].w);
                acc[i][0] = ffma2(p, make_float2(wv[3].x, wv[3].y), acc[i][0]);
                acc[i][1] = ffma2(p, make_float2(wv[3].z, wv[3].w), acc[i][1]);
            }
        }
    }

    // ---- epilogue ----
    __syncthreads();
    float* wkv_s = wsm;                     // 128*64 floats overlay
    int n0 = lane * 2;
    int n1 = n0 + 1;
#pragma unroll
    for (int i = 0; i < 8; i++) {
        int r = warp * 8 + i;
        int t = t0 + r;
        float mu = mu_s[r], inv = inv_s[r];
        float k0 = inv * (acc[i][0].x - mu * g_wsum[2 * n0])     + g_lbsum[2 * n0];
        float v0 = inv * (acc[i][0].y - mu * g_wsum[2 * n0 + 1]) + g_lbsum[2 * n0 + 1];
        float wk0 = expf(-g_exptf[n0] * k0) * v0;
        float k1 = inv * (acc[i][1].x - mu * g_wsum[2 * n1])     + g_lbsum[2 * n1];
        float v1 = inv * (acc[i][1].y - mu * g_wsum[2 * n1 + 1]) + g_lbsum[2 * n1 + 1];
        float wk1 = expf(-g_exptf[n1] * k1) * v1;
        float2 wv = make_float2(wk0, wk1);
        *reinterpret_cast<float2*>(&g_wkv[((size_t)(b * SS) + t) * NN + n0]) = wv;
        *reinterpret_cast<float2*>(&wkv_s[r * NN + n0]) = wv;
    }
    __syncthreads();
    if (tid < 256) {
        int sub = tid >> 6;
        int n = tid & 63;
        float w = g_w[n];
        float a = 0.f;
#pragma unroll
        for (int r = 0; r < 32; r++) a = a * w + wkv_s[(sub * 32 + r) * NN + n];
        g_chunk[((size_t)b * NCH + cb * 4 + sub) * NN + n] = a;
    }
}

// ---------------- carry prefix over chunks (batched loads for MLP) ----------------
__global__ void scan_carry(const float* __restrict__ td, float* __restrict__ lastout,
                           int write_last) {
    int tid = threadIdx.x;                  // 512 threads
    int n = tid & (NN - 1);
    int b = tid >> 6;
    float wL = expf((float)CHL * td[n]);
    float carry = 0.f;
    for (int c0 = 0; c0 < NCH; c0 += 8) {
        float v[8];
#pragma unroll
        for (int i = 0; i < 8; i++) v[i] = g_chunk[((size_t)b * NCH + c0 + i) * NN + n];
#pragma unroll
        for (int i = 0; i < 8; i++) {
            g_carry[((size_t)b * NCH + c0 + i) * NN + n] = carry;
            carry = carry * wL + v[i];
        }
    }
    if (write_last) lastout[b * NN + n] = carry;
}

// ---------------- kernel C: fused scan + output projection ----------------
// grid: BB*(SS/32) = 1024 blocks, 512 threads; thread owns d0=tid, d1=tid+512
// ow read from L2 via __ldg on g_owQ; smem: wk[32*64] | sT[64*36]
#define SPITCH 36
__global__ void __launch_bounds__(512, 1)
kernelC(float* __restrict__ out) {
    __shared__ float wk[TILE_C * NN];       // 2048
    __shared__ float sT[NN * SPITCH];       // 2304

    int b = blockIdx.x >> 7;
    int c = blockIdx.x & 127;
    int t0 = c * TILE_C;
    int tid = threadIdx.x;

    // stage wkv tile
    reinterpret_cast<float4*>(wk)[tid] =
        reinterpret_cast<const float4*>(&g_wkv[((size_t)(b * SS) + t0) * NN])[tid];
    __syncthreads();

    // scan: thread n produces states for 32 rows, stored transposed
    if (tid < NN) {
        int n = tid;
        float w = g_w[n];
        float st = g_carry[((size_t)b * NCH + c) * NN + n];
#pragma unroll
        for (int r = 0; r < TILE_C; r++) {
            st = st * w + wk[r * NN + n];
            sT[n * SPITCH + r] = st;
        }
    }
    __syncthreads();

    // GEMM: acc[rp][dd], rp = row-pair 0..15, dd: d0=tid, d1=tid+512
    float2 acc[16][2];
#pragma unroll
    for (int rp = 0; rp < 16; rp++) { acc[rp][0] = make_float2(0.f, 0.f); acc[rp][1] = make_float2(0.f, 0.f); }

#pragma unroll 2
    for (int n4 = 0; n4 < 16; n4++) {
        float4 wA = __ldg(&g_owQ[n4 * 1024 + tid]);          // w[d0][4n4..+3]
        float4 wB = __ldg(&g_owQ[n4 * 1024 + 512 + tid]);    // w[d1][4n4..+3]
#pragma unroll
        for (int j = 0; j < 4; j++) {
            int n = 4 * n4 + j;
            float wa = (j == 0) ? wA.x : (j == 1) ? wA.y : (j == 2) ? wA.z : wA.w;
            float wb = (j == 0) ? wB.x : (j == 1) ? wB.y : (j == 2) ? wB.z : wB.w;
            float2 wa2 = make_float2(wa, wa);
            float2 wb2 = make_float2(wb, wb);
            const float* sb = &sT[n * SPITCH];
#pragma unroll
            for (int rq = 0; rq < 8; rq++) {
                float4 s4 = *reinterpret_cast<const float4*>(sb + 4 * rq);
                float2 slo = make_float2(s4.x, s4.y);
                float2 shi = make_float2(s4.z, s4.w);
                acc[2 * rq][0]     = ffma2(slo, wa2, acc[2 * rq][0]);
                acc[2 * rq][1]     = ffma2(slo, wb2, acc[2 * rq][1]);
                acc[2 * rq + 1][0] = ffma2(shi, wa2, acc[2 * rq + 1][0]);
                acc[2 * rq + 1][1] = ffma2(shi, wb2, acc[2 * rq + 1][1]);
            }
        }
    }

    float* ob = out + ((size_t)(b * SS) + t0) * DD;
#pragma unroll
    for (int rp = 0; rp < 16; rp++) {
        ob[(size_t)(2 * rp) * DD + tid]           = acc[rp][0].x;
        ob[(size_t)(2 * rp + 1) * DD + tid]       = acc[rp][0].y;
        ob[(size_t)(2 * rp) * DD + 512 + tid]     = acc[rp][1].x;
        ob[(size_t)(2 * rp + 1) * DD + 512 + tid] = acc[rp][1].y;
    }
}

// ---------------- launch ----------------
extern "C" void kernel_launch(void* const* d_in, const int* in_sizes, int n_in,
                              void* d_out, int out_size) {
    const float* x   = (const float*)d_in[0];
    const float* td  = (const float*)d_in[1];
    const float* tf  = (const float*)d_in[2];
    const float* kw  = (const float*)d_in[3];
    const float* vw  = (const float*)d_in[4];
    const float* ow  = (const float*)d_in[5];
    const float* tsg = (const float*)d_in[6];
    const float* lnw = (const float*)d_in[7];
    const float* lnb = (const float*)d_in[8];
    float* out = (float*)d_out;

    const int SMEM_A = (16384 + 16384 + 256) * (int)sizeof(float);   // 132KB
    cudaFuncSetAttribute(kernelA, cudaFuncAttributeMaxDynamicSharedMemorySize, SMEM_A);

    prep_a<<<(DD * 128) / 256, 256>>>(kw, vw, lnw, tsg, td, tf);
    prep_ow<<<64, 256>>>(ow);
    prep_b<<<128, 256>>>(kw, vw, lnb);
    kernelA<<<BB * (SS / TILE_A), 512, SMEM_A>>>(x);
    int write_last = (out_size >= BB * SS * DD + BB * NN) ? 1 : 0;
    scan_carry<<<1, 512>>>(td, out + (size_t)BB * SS * DD, write_last);
    kernelC<<<BB * (SS / TILE_C), 512>>>(out);
}